// round 16
// baseline (speedup 1.0000x reference)
#include <cuda_runtime.h>
#include <cuda_bf16.h>
#include <cuda_fp16.h>
#include <cstdint>
#include <cstddef>

// ---------------------------------------------------------------------------
// DSDModules via mma.sync bf16 m16n8k16. v12 = frozen convs (single band +
// 3-stage B ring conv1/2, PRELOAD conv3/4) + cross-pixel-pair tap dedup in
// the deformable gather: each unique sample row is fetched once per adjacent
// pixel pair and applied to both pixels (exact; zero-weight padding).
// ---------------------------------------------------------------------------

#define NP 4096

// ---- scratch offsets (float units) -----------------------------------------
#define OFF_INT  0ull            // inTb  [4096][512]  bf16
#define OFF_GART 1048576ull      // garTh [4096][256]  fp16
#define OFF_WB1  1572864ull      // wb1   [8][128][4608] bf16
#define OFF_WB2  3932160ull      // wb2   [8][64][1152]  bf16
#define OFF_WB3  4227072ull      // wb3   [8][32][576]   bf16
#define OFF_WB4  4300800ull      // wb4   [8][32][576]   bf16 (cin-padded)
#define OFF_H1   4374528ull      // h1 [8][4096][128] bf16
#define OFF_H2   6471680ull      // h2 [8][4096][64]  bf16
#define OFF_H3   7520256ull      // h3 [8][4096][64]  bf16 (upper 32 stay 0)
#define OFF_OA   8568832ull      // oa [8][18][4096]  fp32
#define SCRATCH_FLOATS 9158656ull

__device__ __align__(1024) float g_scratch[SCRATCH_FLOATS];

// ---- helpers ---------------------------------------------------------------
__device__ __forceinline__ uint32_t smem_u32(const void* p) {
    uint32_t a;
    asm("{ .reg .u64 t; cvta.to.shared.u64 t, %1; cvt.u32.u64 %0, t; }"
        : "=r"(a) : "l"(p));
    return a;
}
__device__ __forceinline__ void cp16(uint32_t sa, const void* g, bool ok) {
    int sz = ok ? 16 : 0;
    asm volatile("cp.async.cg.shared.global [%0], [%1], 16, %2;"
                 :: "r"(sa), "l"(g), "r"(sz) : "memory");
}
#define CP_COMMIT() asm volatile("cp.async.commit_group;" ::: "memory")
#define CP_WAIT(n)  asm volatile("cp.async.wait_group %0;" :: "n"(n) : "memory")

__device__ __forceinline__ void ldsm4(uint32_t* r, uint32_t addr) {
    asm volatile("ldmatrix.sync.aligned.m8n8.x4.shared.b16 {%0,%1,%2,%3}, [%4];"
                 : "=r"(r[0]), "=r"(r[1]), "=r"(r[2]), "=r"(r[3]) : "r"(addr));
}
__device__ __forceinline__ void mma_bf16(float* c, const uint32_t* a, const uint32_t* b) {
    asm volatile(
        "mma.sync.aligned.m16n8k16.row.col.f32.bf16.bf16.f32 "
        "{%0,%1,%2,%3}, {%4,%5,%6,%7}, {%8,%9}, {%0,%1,%2,%3};"
        : "+f"(c[0]), "+f"(c[1]), "+f"(c[2]), "+f"(c[3])
        : "r"(a[0]), "r"(a[1]), "r"(a[2]), "r"(a[3]), "r"(b[0]), "r"(b[1]));
}

// ---------------------------------------------------------------------------
// Fused prep kernel: transpose + all 4 weight reorders (templated dims).
// ---------------------------------------------------------------------------
template<int CINR, int CINP, int COUTR, int COUTP>
__device__ void wb_region(const float* __restrict__ W, __nv_bfloat16* __restrict__ Wb,
                          size_t tidg, size_t nthreads) {
    constexpr int K = CINP * 9;
    constexpr size_t total = (size_t)8 * COUTP * K;
    for (size_t i = tidg; i < total; i += nthreads) {
        int k = (int)(i % K);
        size_t rem = i / K;
        int m = (int)(rem % COUTP);
        int g = (int)(rem / COUTP);
        int tap = k / CINP, cin = k - tap * CINP;
        float v = 0.f;
        if (m < COUTR && cin < CINR)
            v = W[((size_t)(g * COUTR + m) * CINR + cin) * 9 + tap];
        Wb[i] = __float2bfloat16_rn(v);
    }
}

__global__ __launch_bounds__(256)
void prep_all(const float* __restrict__ gar, const float* __restrict__ cond,
              __nv_bfloat16* __restrict__ inTb, __half* __restrict__ garTh,
              const float* __restrict__ W1, __nv_bfloat16* __restrict__ wb1,
              const float* __restrict__ W2, __nv_bfloat16* __restrict__ wb2,
              const float* __restrict__ W3, __nv_bfloat16* __restrict__ wb3,
              const float* __restrict__ W4, __nv_bfloat16* __restrict__ wb4) {
    if (blockIdx.x < 2048) {
        __shared__ float tile[32][33];
        int tx = threadIdx.x & 31;
        int ty = threadIdx.x >> 5;
        int p0 = (blockIdx.x & 127) * 32;
        int c0 = (blockIdx.x >> 7) * 32;
        for (int i = ty; i < 32; i += 8) {
            int c = c0 + i;
            const float* src = (c < 256) ? (gar + (size_t)c * NP)
                                         : (cond + (size_t)(c - 256) * NP);
            tile[i][tx] = src[p0 + tx];
        }
        __syncthreads();
        for (int i = ty; i < 32; i += 8) {
            float v = tile[tx][i];
            int pix = p0 + i, c = c0 + tx;
            inTb[(size_t)pix * 512 + c] = __float2bfloat16_rn(v);
            if (c0 < 256)
                garTh[(size_t)pix * 256 + c] = __float2half_rn(v);
        }
    } else {
        size_t tidg = (size_t)(blockIdx.x - 2048) * 256 + threadIdx.x;
        size_t nt   = (size_t)2752 * 256;
        wb_region<512, 512, 128, 128>(W1, wb1, tidg, nt);
        wb_region<128, 128,  64,  64>(W2, wb2, tidg, nt);
        wb_region< 64,  64,  32,  32>(W3, wb3, tidg, nt);
        wb_region< 32,  64,  18,  32>(W4, wb4, tidg, nt);
    }
}

// ---------------------------------------------------------------------------
// bf16 band-reuse implicit-GEMM 3x3 conv (unchanged, frozen since R13).
// ---------------------------------------------------------------------------
template<int CIN, int COUT, int COUT_REAL, int OUT_STRIDE, bool RELU, int OUT_MODE, int MINB>
__global__ __launch_bounds__(128, MINB)
void mconv(const __nv_bfloat16* __restrict__ in, size_t gstride,
           const __nv_bfloat16* __restrict__ Wb, const float* __restrict__ bias,
           void* __restrict__ outv) {
    constexpr int  K       = CIN * 9;
    constexpr int  NCC     = CIN / 64;
    constexpr int  TOT     = NCC * 9;
    constexpr bool PRELOAD = (NCC == 1);
    constexpr int  WN      = COUT / 2;
    constexpr int  NTT     = WN / 8;
    constexpr int  BPIX    = 264;              // 4 rows x 66 cols
    constexpr int  BSTAGE  = BPIX * 128;       // band stage bytes
    constexpr int  BBS     = COUT * 128;       // B stage bytes

    extern __shared__ char sm[];
    uint32_t base = (smem_u32(sm) + 1023u) & ~1023u;

    const int tid  = threadIdx.x;
    const int warp = tid >> 5;
    const int lane = tid & 31;
    const int lq   = lane >> 2;
    const int lc   = lane & 3;
    const int wm   = warp & 1;
    const int wn   = warp >> 1;
    const int tile = blockIdx.x;
    const int g    = blockIdx.y;
    const int y0   = tile * 2 - 1;

    const __nv_bfloat16* src = in + (size_t)g * gstride;
    const __nv_bfloat16* wg  = Wb + (size_t)g * COUT * K;

    const uint32_t bandBase = base;
    const uint32_t bbBase   = base + BSTAGE;   // single band buffer

    float acc[4][NTT][4];
    #pragma unroll
    for (int i = 0; i < 4; i++)
        #pragma unroll
        for (int j = 0; j < NTT; j++)
            #pragma unroll
            for (int q = 0; q < 4; q++) acc[i][j][q] = 0.f;

    auto band_load = [&](int cc) {
        int c0 = cc * 64;
        for (int it = tid; it < BPIX * 8; it += 128) {
            int bp = it >> 3, seg = it & 7;
            int br = bp / 66;
            int col = bp - br * 66;
            int y = y0 + br, x = col - 1;
            bool ok = ((unsigned)y < 64u) & ((unsigned)x < 64u);
            int pix = ok ? (y * 64 + x) : 0;
            const __nv_bfloat16* gp = src + (size_t)pix * CIN + c0 + seg * 8;
            cp16(bandBase + (uint32_t)(bp * 128 + ((seg * 16) ^ ((bp & 7) * 16))), gp, ok);
        }
    };
    auto b_load = [&](int kc, int stage) {
        int cc = kc / 9;
        int koff = (kc - cc * 9) * CIN + cc * 64;
        for (int it = tid; it < COUT * 8; it += 128) {
            int m = it >> 3, seg = it & 7;
            const __nv_bfloat16* gp = wg + (size_t)m * K + koff + seg * 8;
            cp16(bbBase + stage * BBS
                 + (uint32_t)(m * 128 + ((seg * 16) ^ ((m & 7) * 16))), gp, true);
        }
    };

    // lane-constant ldmatrix address components (A fragments)
    const int amat  = lane >> 3;
    const int aroff = (lane & 7) + (amat & 1) * 8;
    const int akb   = (amat >> 1) * 16;

    auto compute = [&](int tap, int bstage) {
        int r = tap / 3, s = tap - 3 * (tap / 3);
        int bbase0 = (wm + r) * 66 + s;
        uint32_t aS = bandBase;
        uint32_t bS = bbBase + bstage * BBS;
        #pragma unroll
        for (int seg = 0; seg < 4; seg++) {
            uint32_t af[4][4];
            #pragma unroll
            for (int mt = 0; mt < 4; mt++) {
                int bp = bbase0 + mt * 16 + aroff;
                uint32_t addr = aS + (uint32_t)(bp * 128 + ((seg * 32 + akb) ^ ((bp & 7) * 16)));
                ldsm4(af[mt], addr);
            }
            uint32_t bf[NTT][2];
            #pragma unroll
            for (int ntp = 0; ntp < NTT / 2; ntp++) {
                int n = wn * WN + (ntp * 2 + (lane >> 4)) * 8 + (lane & 7);
                int kb = ((lane >> 3) & 1) * 16;
                uint32_t addr = bS + (uint32_t)(n * 128 + ((seg * 32 + kb) ^ ((n & 7) * 16)));
                uint32_t tmp[4];
                ldsm4(tmp, addr);
                bf[2 * ntp][0] = tmp[0]; bf[2 * ntp][1] = tmp[1];
                bf[2 * ntp + 1][0] = tmp[2]; bf[2 * ntp + 1][1] = tmp[3];
            }
            #pragma unroll
            for (int mt = 0; mt < 4; mt++)
                #pragma unroll
                for (int nt = 0; nt < NTT; nt++)
                    mma_bf16(acc[mt][nt], af[mt], bf[nt]);
        }
    };

    if (PRELOAD) {
        band_load(0);
        #pragma unroll
        for (int t9 = 0; t9 < 9; t9++) b_load(t9, t9);   // BBS ring of 9
        CP_COMMIT();
        CP_WAIT(0);
        __syncthreads();
        #pragma unroll
        for (int tap = 0; tap < 9; tap++)
            compute(tap, tap);
    } else {
        // Single band + 3-stage B ring, one commit per iteration, 2-ahead.
        band_load(0); CP_COMMIT();
        b_load(0, 0); CP_COMMIT();
        b_load(1, 1); CP_COMMIT();
        for (int kc = 0; kc < TOT; kc++) {
            int cc  = kc / 9;
            int tap = kc - cc * 9;
            if (tap == 0 && cc > 0) {
                __syncthreads();          // all warps done reading old band
                band_load(cc); CP_COMMIT();
                CP_WAIT(0);               // band cc + pending B chunks arrived
            } else {
                CP_WAIT(1);               // B kc arrived (kc+1 may be inflight)
            }
            __syncthreads();              // publish across warps
            int nb = kc + 2;
            if (nb < TOT) { b_load(nb, nb % 3); CP_COMMIT(); }
            compute(tap, kc % 3);
        }
    }

    // Epilogue: bias + lrelu, store.
    #pragma unroll
    for (int mt = 0; mt < 4; mt++) {
        int prow = tile * 128 + wm * 64 + mt * 16 + lq;
        #pragma unroll
        for (int nt = 0; nt < NTT; nt++) {
            int n0 = wn * WN + nt * 8 + lc * 2;
            float b0 = (n0     < COUT_REAL) ? bias[g * COUT_REAL + n0]     : 0.f;
            float b1 = (n0 + 1 < COUT_REAL) ? bias[g * COUT_REAL + n0 + 1] : 0.f;
            #pragma unroll
            for (int h = 0; h < 2; h++) {
                int p = prow + h * 8;
                float v0 = acc[mt][nt][h * 2]     + b0;
                float v1 = acc[mt][nt][h * 2 + 1] + b1;
                if (RELU) {
                    v0 = (v0 >= 0.f) ? v0 : 0.1f * v0;
                    v1 = (v1 >= 0.f) ? v1 : 0.1f * v1;
                }
                if (OUT_MODE == 0) {
                    __nv_bfloat16* ob = (__nv_bfloat16*)outv;
                    __nv_bfloat162 pr;
                    pr.x = __float2bfloat16_rn(v0);
                    pr.y = __float2bfloat16_rn(v1);
                    *(__nv_bfloat162*)(ob + ((size_t)g * NP + p) * OUT_STRIDE + n0) = pr;
                } else {
                    float* of = (float*)outv;
                    if (n0 < COUT_REAL)
                        of[(size_t)(g * COUT_REAL + n0) * NP + p] = v0;
                    if (n0 + 1 < COUT_REAL)
                        of[(size_t)(g * COUT_REAL + n0 + 1) * NP + p] = v1;
                }
            }
        }
    }
}

// ---------------------------------------------------------------------------
// Final warp/sample kernel v3: per-pixel dedup + cross-pixel-pair dedup.
//   Phase 1 (24 thr): softmax + bilinear taps (attn folded) per (pixel,k).
//   Phase 2a (32 thr): merge 24 taps per (pixel,group) by integer position.
//   Phase 2b (16 thr): merge the two lists of each adjacent pixel PAIR into
//            one list with a weight pair (exact; missing pixel gets w=0).
//   Phase 3: warp = (pair, group-pair); lane owns 8 channels; each unique
//            row fetched ONCE per pair (float4) and FMA'd into both pixels.
//   Phase 4 (256 thr = channels): sum 4 group-pair partials, float4 store.
// ---------------------------------------------------------------------------
__global__ __launch_bounds__(256)
void warp_kernel(const float* __restrict__ oa, const __half* __restrict__ garTh,
                 const float* __restrict__ mask, float* __restrict__ out) {
    __shared__ int   sO[4][192];
    __shared__ float sA[4][192];
    __shared__ int   sPosC[4][8][24];
    __shared__ float sWC[4][8][24];
    __shared__ int   sCnt[4][8];
    __shared__ int   sPosM[2][8][48];
    __shared__ float sWM[2][8][48][2];
    __shared__ int   sCntM[2][8];
    __shared__ float sPart[4][4][256];   // [gpair][pixel][channel]

    const int pix0 = blockIdx.x * 4;
    const int tt = threadIdx.x;

    if (tt < 24) {
        int p = tt / 6, k = tt - (tt / 6) * 6;
        int pix = pix0 + p;
        float fx = (float)(pix & 63);
        float fy = (float)(pix >> 6);
        float lg[8], ox[8], oy[8];
        #pragma unroll
        for (int g = 0; g < 8; g++) {
            const float* base = oa + (size_t)g * 18 * NP + pix;
            lg[g] = base[(12 + k) * NP];
            ox[g] = base[(2 * k) * NP];
            oy[g] = base[(2 * k + 1) * NP];
        }
        float m = lg[0];
        #pragma unroll
        for (int g = 1; g < 8; g++) m = fmaxf(m, lg[g]);
        float s = 0.f;
        #pragma unroll
        for (int g = 0; g < 8; g++) { lg[g] = expf(lg[g] - m); s += lg[g]; }
        float inv = 1.f / s;
        #pragma unroll
        for (int g = 0; g < 8; g++) {
            float attn = lg[g] * inv;
            float xs = fminf(fmaxf((fx + ox[g]) * (64.0f / 63.0f) - 0.5f, 0.f), 63.f);
            float ys = fminf(fmaxf((fy + oy[g]) * (64.0f / 63.0f) - 0.5f, 0.f), 63.f);
            float x0f = floorf(xs), y0f = floorf(ys);
            float wx = xs - x0f, wy = ys - y0f;
            int x0 = (int)x0f, y0 = (int)y0f;
            int x1 = min(x0 + 1, 63), y1 = min(y0 + 1, 63);
            int q = (p * 6 + k) * 8 + g;
            sO[0][q] = (y0 * 64 + x0) * 256;
            sO[1][q] = (y0 * 64 + x1) * 256;
            sO[2][q] = (y1 * 64 + x0) * 256;
            sO[3][q] = (y1 * 64 + x1) * 256;
            sA[0][q] = attn * (1.f - wy) * (1.f - wx);
            sA[1][q] = attn * (1.f - wy) * wx;
            sA[2][q] = attn * wy * (1.f - wx);
            sA[3][q] = attn * wy * wx;
        }
    }
    __syncthreads();

    if (tt < 32) {
        int p = tt >> 3, g = tt & 7;
        int cnt = 0;
        for (int k = 0; k < 6; k++) {
            int qbase = (p * 6 + k) * 8 + g;
            #pragma unroll
            for (int q = 0; q < 4; q++) {
                int   po = sO[q][qbase];
                float ww = sA[q][qbase];
                int j = 0;
                for (; j < cnt; j++) {
                    if (sPosC[p][g][j] == po) { sWC[p][g][j] += ww; break; }
                }
                if (j == cnt) { sPosC[p][g][cnt] = po; sWC[p][g][cnt] = ww; cnt++; }
            }
        }
        sCnt[p][g] = cnt;
    }
    __syncthreads();

    // Phase 2b: merge pixel pairs (16 threads = pair pr x group g).
    if (tt < 16) {
        int pr = tt >> 3, g = tt & 7;
        int cm = 0;
        #pragma unroll
        for (int pp = 0; pp < 2; pp++) {
            int p = pr * 2 + pp;
            int cnt = sCnt[p][g];
            for (int j = 0; j < cnt; j++) {
                int   po = sPosC[p][g][j];
                float ww = sWC[p][g][j];
                int i = 0;
                for (; i < cm; i++) {
                    if (sPosM[pr][g][i] == po) { sWM[pr][g][i][pp] += ww; break; }
                }
                if (i == cm) {
                    sPosM[pr][g][cm] = po;
                    sWM[pr][g][cm][pp]     = ww;
                    sWM[pr][g][cm][pp ^ 1] = 0.f;
                    cm++;
                }
            }
        }
        sCntM[pr][g] = cm;
    }
    __syncthreads();

    // Phase 3: warp = (pair pr, group-pair gp); lane owns 8 channels.
    {
        const int w    = tt >> 5;
        const int lane = tt & 31;
        const int pr   = w >> 2;          // 0..1
        const int gp   = w & 3;           // 0..3 (groups 2gp, 2gp+1)
        const int c8   = lane * 8;

        float accPx[2][8];
        #pragma unroll
        for (int pp = 0; pp < 2; pp++)
            #pragma unroll
            for (int i = 0; i < 8; i++) accPx[pp][i] = 0.f;

        #pragma unroll
        for (int gg = 0; gg < 2; gg++) {
            int g = gp * 2 + gg;
            int cnt = sCntM[pr][g];
            float gacc[2][8];
            #pragma unroll
            for (int pp = 0; pp < 2; pp++)
                #pragma unroll
                for (int i = 0; i < 8; i++) gacc[pp][i] = 0.f;
            for (int j = 0; j < cnt; j++) {
                float4 raw = *(const float4*)(garTh + sPosM[pr][g][j] + c8);
                float w0 = sWM[pr][g][j][0];
                float w1 = sWM[pr][g][j][1];
                const __half2* hp = (const __half2*)&raw;
                #pragma unroll
                for (int q = 0; q < 4; q++) {
                    float2 f = __half22float2(hp[q]);
                    gacc[0][q * 2]     += w0 * f.x;
                    gacc[0][q * 2 + 1] += w0 * f.y;
                    gacc[1][q * 2]     += w1 * f.x;
                    gacc[1][q * 2 + 1] += w1 * f.y;
                }
            }
            float4 mk0 = *(const float4*)(mask + g * 256 + c8);
            float4 mk1 = *(const float4*)(mask + g * 256 + c8 + 4);
            float mk[8] = { mk0.x, mk0.y, mk0.z, mk0.w, mk1.x, mk1.y, mk1.z, mk1.w };
            #pragma unroll
            for (int pp = 0; pp < 2; pp++)
                #pragma unroll
                for (int i = 0; i < 8; i++)
                    accPx[pp][i] += gacc[pp][i] * mk[i];
        }
        #pragma unroll
        for (int pp = 0; pp < 2; pp++)
            #pragma unroll
            for (int i = 0; i < 8; i++)
                sPart[gp][pr * 2 + pp][c8 + i] = accPx[pp][i];
    }
    __syncthreads();

    // Phase 4: sum the four group-pair partials, coalesced 16B row store.
    {
        float4 v;
        v.x = sPart[0][0][tt] + sPart[1][0][tt] + sPart[2][0][tt] + sPart[3][0][tt];
        v.y = sPart[0][1][tt] + sPart[1][1][tt] + sPart[2][1][tt] + sPart[3][1][tt];
        v.z = sPart[0][2][tt] + sPart[1][2][tt] + sPart[2][2][tt] + sPart[3][2][tt];
        v.w = sPart[0][3][tt] + sPart[1][3][tt] + sPart[2][3][tt] + sPart[3][3][tt];
        *(float4*)(out + (size_t)tt * NP + pix0) = v;
    }
}

// ---------------------------------------------------------------------------
extern "C" void kernel_launch(void* const* d_in, const int* in_sizes, int n_in,
                              void* d_out, int out_size) {
    const float* gar  = (const float*)d_in[0];
    const float* cond = (const float*)d_in[1];
    const float* mask = (const float*)d_in[2];
    const float* W1   = (const float*)d_in[3];
    const float* b1   = (const float*)d_in[4];
    const float* W2   = (const float*)d_in[5];
    const float* b2   = (const float*)d_in[6];
    const float* W3   = (const float*)d_in[7];
    const float* b3   = (const float*)d_in[8];
    const float* W4   = (const float*)d_in[9];
    const float* b4   = (const float*)d_in[10];
    float* out = (float*)d_out;

    float* S = nullptr;
    cudaGetSymbolAddress((void**)&S, g_scratch);
    __nv_bfloat16* inTb  = (__nv_bfloat16*)(S + OFF_INT);
    __half*        garTh = (__half*)       (S + OFF_GART);
    __nv_bfloat16* wb1   = (__nv_bfloat16*)(S + OFF_WB1);
    __nv_bfloat16* wb2   = (__nv_bfloat16*)(S + OFF_WB2);
    __nv_bfloat16* wb3   = (__nv_bfloat16*)(S + OFF_WB3);
    __nv_bfloat16* wb4   = (__nv_bfloat16*)(S + OFF_WB4);
    __nv_bfloat16* h1    = (__nv_bfloat16*)(S + OFF_H1);
    __nv_bfloat16* h2    = (__nv_bfloat16*)(S + OFF_H2);
    __nv_bfloat16* h3    = (__nv_bfloat16*)(S + OFF_H3);
    float*         oa    = S + OFF_OA;

    // dynamic smem: band + B stages (+1KB align slack)
    const int SM1  = 264 * 128 + 3 * 128 * 128 + 1024;  // 83968 -> 2 CTAs/SM
    const int SM2  = 264 * 128 + 3 * 64 * 128 + 1024;   // 59392 -> 3 CTAs/SM
    const int SM34 = 264 * 128 + 9 * 32 * 128 + 1024;   // 71680 -> 3 CTAs/SM

    cudaFuncSetAttribute(mconv<512,128,128,128,true ,0,2>, cudaFuncAttributeMaxDynamicSharedMemorySize, SM1);
    cudaFuncSetAttribute(mconv<128, 64, 64, 64,true ,0,3>, cudaFuncAttributeMaxDynamicSharedMemorySize, SM2);
    cudaFuncSetAttribute(mconv< 64, 32, 32, 64,true ,0,3>, cudaFuncAttributeMaxDynamicSharedMemorySize, SM34);
    cudaFuncSetAttribute(mconv< 64, 32, 18,  1,false,1,3>, cudaFuncAttributeMaxDynamicSharedMemorySize, SM34);

    prep_all<<<2048 + 2752, 256>>>(gar, cond, inTb, garTh,
                                   W1, wb1, W2, wb2, W3, wb3, W4, wb4);

    mconv<512,128,128,128,true ,0,2><<<dim3(32, 8), 128, SM1 >>>(inTb, 0,               wb1, b1, h1);
    mconv<128, 64, 64, 64,true ,0,3><<<dim3(32, 8), 128, SM2 >>>(h1, (size_t)NP * 128,  wb2, b2, h2);
    mconv< 64, 32, 32, 64,true ,0,3><<<dim3(32, 8), 128, SM34>>>(h2, (size_t)NP * 64,   wb3, b3, h3);
    mconv< 64, 32, 18,  1,false,1,3><<<dim3(32, 8), 128, SM34>>>(h3, (size_t)NP * 64,   wb4, b4, oa);

    warp_kernel<<<NP / 4, 256>>>(oa, garTh, mask, out);
}

// round 17
// speedup vs baseline: 1.0642x; 1.0642x over previous
#include <cuda_runtime.h>
#include <cuda_bf16.h>
#include <cuda_fp16.h>
#include <cstdint>
#include <cstddef>

// ---------------------------------------------------------------------------
// DSDModules via mma.sync bf16 m16n8k16. v13 = R15 (best measured) with one
// change: warp_kernel phase 1 fully parallelized (192 threads = px x k x g,
// cross-group softmax via shfl_xor butterflies in aligned 8-lane subgroups).
// Convs frozen at their mma.sync HMMA ceiling.
// ---------------------------------------------------------------------------

#define NP 4096

// ---- scratch offsets (float units) -----------------------------------------
#define OFF_INT  0ull            // inTb  [4096][512]  bf16
#define OFF_GART 1048576ull      // garTh [4096][256]  fp16
#define OFF_WB1  1572864ull      // wb1   [8][128][4608] bf16
#define OFF_WB2  3932160ull      // wb2   [8][64][1152]  bf16
#define OFF_WB3  4227072ull      // wb3   [8][32][576]   bf16
#define OFF_WB4  4300800ull      // wb4   [8][32][576]   bf16 (cin-padded)
#define OFF_H1   4374528ull      // h1 [8][4096][128] bf16
#define OFF_H2   6471680ull      // h2 [8][4096][64]  bf16
#define OFF_H3   7520256ull      // h3 [8][4096][64]  bf16 (upper 32 stay 0)
#define OFF_OA   8568832ull      // oa [8][18][4096]  fp32
#define SCRATCH_FLOATS 9158656ull

__device__ __align__(1024) float g_scratch[SCRATCH_FLOATS];

// ---- helpers ---------------------------------------------------------------
__device__ __forceinline__ uint32_t smem_u32(const void* p) {
    uint32_t a;
    asm("{ .reg .u64 t; cvta.to.shared.u64 t, %1; cvt.u32.u64 %0, t; }"
        : "=r"(a) : "l"(p));
    return a;
}
__device__ __forceinline__ void cp16(uint32_t sa, const void* g, bool ok) {
    int sz = ok ? 16 : 0;
    asm volatile("cp.async.cg.shared.global [%0], [%1], 16, %2;"
                 :: "r"(sa), "l"(g), "r"(sz) : "memory");
}
#define CP_COMMIT() asm volatile("cp.async.commit_group;" ::: "memory")
#define CP_WAIT(n)  asm volatile("cp.async.wait_group %0;" :: "n"(n) : "memory")

__device__ __forceinline__ void ldsm4(uint32_t* r, uint32_t addr) {
    asm volatile("ldmatrix.sync.aligned.m8n8.x4.shared.b16 {%0,%1,%2,%3}, [%4];"
                 : "=r"(r[0]), "=r"(r[1]), "=r"(r[2]), "=r"(r[3]) : "r"(addr));
}
__device__ __forceinline__ void mma_bf16(float* c, const uint32_t* a, const uint32_t* b) {
    asm volatile(
        "mma.sync.aligned.m16n8k16.row.col.f32.bf16.bf16.f32 "
        "{%0,%1,%2,%3}, {%4,%5,%6,%7}, {%8,%9}, {%0,%1,%2,%3};"
        : "+f"(c[0]), "+f"(c[1]), "+f"(c[2]), "+f"(c[3])
        : "r"(a[0]), "r"(a[1]), "r"(a[2]), "r"(a[3]), "r"(b[0]), "r"(b[1]));
}

// ---------------------------------------------------------------------------
// Fused prep kernel: transpose + all 4 weight reorders (templated dims).
// ---------------------------------------------------------------------------
template<int CINR, int CINP, int COUTR, int COUTP>
__device__ void wb_region(const float* __restrict__ W, __nv_bfloat16* __restrict__ Wb,
                          size_t tidg, size_t nthreads) {
    constexpr int K = CINP * 9;
    constexpr size_t total = (size_t)8 * COUTP * K;
    for (size_t i = tidg; i < total; i += nthreads) {
        int k = (int)(i % K);
        size_t rem = i / K;
        int m = (int)(rem % COUTP);
        int g = (int)(rem / COUTP);
        int tap = k / CINP, cin = k - tap * CINP;
        float v = 0.f;
        if (m < COUTR && cin < CINR)
            v = W[((size_t)(g * COUTR + m) * CINR + cin) * 9 + tap];
        Wb[i] = __float2bfloat16_rn(v);
    }
}

__global__ __launch_bounds__(256)
void prep_all(const float* __restrict__ gar, const float* __restrict__ cond,
              __nv_bfloat16* __restrict__ inTb, __half* __restrict__ garTh,
              const float* __restrict__ W1, __nv_bfloat16* __restrict__ wb1,
              const float* __restrict__ W2, __nv_bfloat16* __restrict__ wb2,
              const float* __restrict__ W3, __nv_bfloat16* __restrict__ wb3,
              const float* __restrict__ W4, __nv_bfloat16* __restrict__ wb4) {
    if (blockIdx.x < 2048) {
        __shared__ float tile[32][33];
        int tx = threadIdx.x & 31;
        int ty = threadIdx.x >> 5;
        int p0 = (blockIdx.x & 127) * 32;
        int c0 = (blockIdx.x >> 7) * 32;
        for (int i = ty; i < 32; i += 8) {
            int c = c0 + i;
            const float* src = (c < 256) ? (gar + (size_t)c * NP)
                                         : (cond + (size_t)(c - 256) * NP);
            tile[i][tx] = src[p0 + tx];
        }
        __syncthreads();
        for (int i = ty; i < 32; i += 8) {
            float v = tile[tx][i];
            int pix = p0 + i, c = c0 + tx;
            inTb[(size_t)pix * 512 + c] = __float2bfloat16_rn(v);
            if (c0 < 256)
                garTh[(size_t)pix * 256 + c] = __float2half_rn(v);
        }
    } else {
        size_t tidg = (size_t)(blockIdx.x - 2048) * 256 + threadIdx.x;
        size_t nt   = (size_t)2752 * 256;
        wb_region<512, 512, 128, 128>(W1, wb1, tidg, nt);
        wb_region<128, 128,  64,  64>(W2, wb2, tidg, nt);
        wb_region< 64,  64,  32,  32>(W3, wb3, tidg, nt);
        wb_region< 32,  64,  18,  32>(W4, wb4, tidg, nt);
    }
}

// ---------------------------------------------------------------------------
// bf16 band-reuse implicit-GEMM 3x3 conv (unchanged, frozen since R13).
// ---------------------------------------------------------------------------
template<int CIN, int COUT, int COUT_REAL, int OUT_STRIDE, bool RELU, int OUT_MODE, int MINB>
__global__ __launch_bounds__(128, MINB)
void mconv(const __nv_bfloat16* __restrict__ in, size_t gstride,
           const __nv_bfloat16* __restrict__ Wb, const float* __restrict__ bias,
           void* __restrict__ outv) {
    constexpr int  K       = CIN * 9;
    constexpr int  NCC     = CIN / 64;
    constexpr int  TOT     = NCC * 9;
    constexpr bool PRELOAD = (NCC == 1);
    constexpr int  WN      = COUT / 2;
    constexpr int  NTT     = WN / 8;
    constexpr int  BPIX    = 264;              // 4 rows x 66 cols
    constexpr int  BSTAGE  = BPIX * 128;       // band stage bytes
    constexpr int  BBS     = COUT * 128;       // B stage bytes

    extern __shared__ char sm[];
    uint32_t base = (smem_u32(sm) + 1023u) & ~1023u;

    const int tid  = threadIdx.x;
    const int warp = tid >> 5;
    const int lane = tid & 31;
    const int lq   = lane >> 2;
    const int lc   = lane & 3;
    const int wm   = warp & 1;
    const int wn   = warp >> 1;
    const int tile = blockIdx.x;
    const int g    = blockIdx.y;
    const int y0   = tile * 2 - 1;

    const __nv_bfloat16* src = in + (size_t)g * gstride;
    const __nv_bfloat16* wg  = Wb + (size_t)g * COUT * K;

    const uint32_t bandBase = base;
    const uint32_t bbBase   = base + BSTAGE;   // single band buffer

    float acc[4][NTT][4];
    #pragma unroll
    for (int i = 0; i < 4; i++)
        #pragma unroll
        for (int j = 0; j < NTT; j++)
            #pragma unroll
            for (int q = 0; q < 4; q++) acc[i][j][q] = 0.f;

    auto band_load = [&](int cc) {
        int c0 = cc * 64;
        for (int it = tid; it < BPIX * 8; it += 128) {
            int bp = it >> 3, seg = it & 7;
            int br = bp / 66;
            int col = bp - br * 66;
            int y = y0 + br, x = col - 1;
            bool ok = ((unsigned)y < 64u) & ((unsigned)x < 64u);
            int pix = ok ? (y * 64 + x) : 0;
            const __nv_bfloat16* gp = src + (size_t)pix * CIN + c0 + seg * 8;
            cp16(bandBase + (uint32_t)(bp * 128 + ((seg * 16) ^ ((bp & 7) * 16))), gp, ok);
        }
    };
    auto b_load = [&](int kc, int stage) {
        int cc = kc / 9;
        int koff = (kc - cc * 9) * CIN + cc * 64;
        for (int it = tid; it < COUT * 8; it += 128) {
            int m = it >> 3, seg = it & 7;
            const __nv_bfloat16* gp = wg + (size_t)m * K + koff + seg * 8;
            cp16(bbBase + stage * BBS
                 + (uint32_t)(m * 128 + ((seg * 16) ^ ((m & 7) * 16))), gp, true);
        }
    };

    // lane-constant ldmatrix address components (A fragments)
    const int amat  = lane >> 3;
    const int aroff = (lane & 7) + (amat & 1) * 8;
    const int akb   = (amat >> 1) * 16;

    auto compute = [&](int tap, int bstage) {
        int r = tap / 3, s = tap - 3 * (tap / 3);
        int bbase0 = (wm + r) * 66 + s;
        uint32_t aS = bandBase;
        uint32_t bS = bbBase + bstage * BBS;
        #pragma unroll
        for (int seg = 0; seg < 4; seg++) {
            uint32_t af[4][4];
            #pragma unroll
            for (int mt = 0; mt < 4; mt++) {
                int bp = bbase0 + mt * 16 + aroff;
                uint32_t addr = aS + (uint32_t)(bp * 128 + ((seg * 32 + akb) ^ ((bp & 7) * 16)));
                ldsm4(af[mt], addr);
            }
            uint32_t bf[NTT][2];
            #pragma unroll
            for (int ntp = 0; ntp < NTT / 2; ntp++) {
                int n = wn * WN + (ntp * 2 + (lane >> 4)) * 8 + (lane & 7);
                int kb = ((lane >> 3) & 1) * 16;
                uint32_t addr = bS + (uint32_t)(n * 128 + ((seg * 32 + kb) ^ ((n & 7) * 16)));
                uint32_t tmp[4];
                ldsm4(tmp, addr);
                bf[2 * ntp][0] = tmp[0]; bf[2 * ntp][1] = tmp[1];
                bf[2 * ntp + 1][0] = tmp[2]; bf[2 * ntp + 1][1] = tmp[3];
            }
            #pragma unroll
            for (int mt = 0; mt < 4; mt++)
                #pragma unroll
                for (int nt = 0; nt < NTT; nt++)
                    mma_bf16(acc[mt][nt], af[mt], bf[nt]);
        }
    };

    if (PRELOAD) {
        band_load(0);
        #pragma unroll
        for (int t9 = 0; t9 < 9; t9++) b_load(t9, t9);   // BBS ring of 9
        CP_COMMIT();
        CP_WAIT(0);
        __syncthreads();
        #pragma unroll
        for (int tap = 0; tap < 9; tap++)
            compute(tap, tap);
    } else {
        // Single band + 3-stage B ring, one commit per iteration, 2-ahead.
        band_load(0); CP_COMMIT();
        b_load(0, 0); CP_COMMIT();
        b_load(1, 1); CP_COMMIT();
        for (int kc = 0; kc < TOT; kc++) {
            int cc  = kc / 9;
            int tap = kc - cc * 9;
            if (tap == 0 && cc > 0) {
                __syncthreads();          // all warps done reading old band
                band_load(cc); CP_COMMIT();
                CP_WAIT(0);               // band cc + pending B chunks arrived
            } else {
                CP_WAIT(1);               // B kc arrived (kc+1 may be inflight)
            }
            __syncthreads();              // publish across warps
            int nb = kc + 2;
            if (nb < TOT) { b_load(nb, nb % 3); CP_COMMIT(); }
            compute(tap, kc % 3);
        }
    }

    // Epilogue: bias + lrelu, store.
    #pragma unroll
    for (int mt = 0; mt < 4; mt++) {
        int prow = tile * 128 + wm * 64 + mt * 16 + lq;
        #pragma unroll
        for (int nt = 0; nt < NTT; nt++) {
            int n0 = wn * WN + nt * 8 + lc * 2;
            float b0 = (n0     < COUT_REAL) ? bias[g * COUT_REAL + n0]     : 0.f;
            float b1 = (n0 + 1 < COUT_REAL) ? bias[g * COUT_REAL + n0 + 1] : 0.f;
            #pragma unroll
            for (int h = 0; h < 2; h++) {
                int p = prow + h * 8;
                float v0 = acc[mt][nt][h * 2]     + b0;
                float v1 = acc[mt][nt][h * 2 + 1] + b1;
                if (RELU) {
                    v0 = (v0 >= 0.f) ? v0 : 0.1f * v0;
                    v1 = (v1 >= 0.f) ? v1 : 0.1f * v1;
                }
                if (OUT_MODE == 0) {
                    __nv_bfloat16* ob = (__nv_bfloat16*)outv;
                    __nv_bfloat162 pr;
                    pr.x = __float2bfloat16_rn(v0);
                    pr.y = __float2bfloat16_rn(v1);
                    *(__nv_bfloat162*)(ob + ((size_t)g * NP + p) * OUT_STRIDE + n0) = pr;
                } else {
                    float* of = (float*)outv;
                    if (n0 < COUT_REAL)
                        of[(size_t)(g * COUT_REAL + n0) * NP + p] = v0;
                    if (n0 + 1 < COUT_REAL)
                        of[(size_t)(g * COUT_REAL + n0 + 1) * NP + p] = v1;
                }
            }
        }
    }
}

// ---------------------------------------------------------------------------
// Final warp/sample kernel v4 (= R15 with parallel phase 1).
//   Phase 1 (192 thr = px x k x g): each thread 3 LDGs; cross-group softmax
//            via shfl_xor butterflies in aligned 8-lane subgroups.
//   Phase 2 (32 thr): merge 24 taps per (pixel,group) by integer position.
//   Phase 3: warp = (pixel, group-half); lane owns 8 channels (one float4
//            per tap row).
//   Phase 4 (256 thr = channels): sum 2 group-half partials, float4 store.
// ---------------------------------------------------------------------------
__global__ __launch_bounds__(256)
void warp_kernel(const float* __restrict__ oa, const __half* __restrict__ garTh,
                 const float* __restrict__ mask, float* __restrict__ out) {
    __shared__ int   sO[4][192];
    __shared__ float sA[4][192];
    __shared__ int   sPosC[4][8][24];
    __shared__ float sWC[4][8][24];
    __shared__ int   sCnt[4][8];
    __shared__ float sPart[8][256];

    const int pix0 = blockIdx.x * 4;
    const int tt = threadIdx.x;

    // Phase 1: one thread per (pixel, k, g). tt = p*48 + k*8 + g, so each
    // g-octet is an aligned 8-lane subgroup inside one warp.
    if (tt < 192) {
        int p   = tt / 48;
        int rem = tt - p * 48;
        int k   = rem >> 3;
        int g   = rem & 7;
        int pix = pix0 + p;
        float fx = (float)(pix & 63);
        float fy = (float)(pix >> 6);

        const float* base = oa + (size_t)g * 18 * NP + pix;
        float lg = base[(12 + k) * NP];
        float ox = base[(2 * k) * NP];
        float oy = base[(2 * k + 1) * NP];

        float m = lg;
        #pragma unroll
        for (int d = 1; d < 8; d <<= 1)
            m = fmaxf(m, __shfl_xor_sync(0xffffffffu, m, d));
        float e = expf(lg - m);
        float s = e;
        #pragma unroll
        for (int d = 1; d < 8; d <<= 1)
            s += __shfl_xor_sync(0xffffffffu, s, d);
        float attn = e / s;

        float xs = fminf(fmaxf((fx + ox) * (64.0f / 63.0f) - 0.5f, 0.f), 63.f);
        float ys = fminf(fmaxf((fy + oy) * (64.0f / 63.0f) - 0.5f, 0.f), 63.f);
        float x0f = floorf(xs), y0f = floorf(ys);
        float wx = xs - x0f, wy = ys - y0f;
        int x0 = (int)x0f, y0 = (int)y0f;
        int x1 = min(x0 + 1, 63), y1 = min(y0 + 1, 63);
        int q = (p * 6 + k) * 8 + g;
        sO[0][q] = (y0 * 64 + x0) * 256;
        sO[1][q] = (y0 * 64 + x1) * 256;
        sO[2][q] = (y1 * 64 + x0) * 256;
        sO[3][q] = (y1 * 64 + x1) * 256;
        sA[0][q] = attn * (1.f - wy) * (1.f - wx);
        sA[1][q] = attn * (1.f - wy) * wx;
        sA[2][q] = attn * wy * (1.f - wx);
        sA[3][q] = attn * wy * wx;
    }
    __syncthreads();

    if (tt < 32) {
        int p = tt >> 3, g = tt & 7;
        int cnt = 0;
        for (int k = 0; k < 6; k++) {
            int qbase = (p * 6 + k) * 8 + g;
            #pragma unroll
            for (int q = 0; q < 4; q++) {
                int   po = sO[q][qbase];
                float ww = sA[q][qbase];
                int j = 0;
                for (; j < cnt; j++) {
                    if (sPosC[p][g][j] == po) { sWC[p][g][j] += ww; break; }
                }
                if (j == cnt) { sPosC[p][g][cnt] = po; sWC[p][g][cnt] = ww; cnt++; }
            }
        }
        sCnt[p][g] = cnt;
    }
    __syncthreads();

    // Phase 3: warp = (pixel, group-half); lane owns 8 channels (one float4).
    {
        const int w    = tt >> 5;
        const int lane = tt & 31;
        const int p    = w >> 1;
        const int g0   = (w & 1) * 4;
        const int c8   = lane * 8;

        float acc8[8];
        #pragma unroll
        for (int i = 0; i < 8; i++) acc8[i] = 0.f;

        #pragma unroll
        for (int gg = 0; gg < 4; gg++) {
            int g = g0 + gg;
            int cnt = sCnt[p][g];
            float gacc[8];
            #pragma unroll
            for (int i = 0; i < 8; i++) gacc[i] = 0.f;
            for (int j = 0; j < cnt; j++) {
                float4 raw = *(const float4*)(garTh + sPosC[p][g][j] + c8);
                float wj = sWC[p][g][j];
                const __half2* hp = (const __half2*)&raw;
                #pragma unroll
                for (int q = 0; q < 4; q++) {
                    float2 f = __half22float2(hp[q]);
                    gacc[q * 2]     += wj * f.x;
                    gacc[q * 2 + 1] += wj * f.y;
                }
            }
            float4 mk0 = *(const float4*)(mask + g * 256 + c8);
            float4 mk1 = *(const float4*)(mask + g * 256 + c8 + 4);
            acc8[0] += gacc[0] * mk0.x;  acc8[1] += gacc[1] * mk0.y;
            acc8[2] += gacc[2] * mk0.z;  acc8[3] += gacc[3] * mk0.w;
            acc8[4] += gacc[4] * mk1.x;  acc8[5] += gacc[5] * mk1.y;
            acc8[6] += gacc[6] * mk1.z;  acc8[7] += gacc[7] * mk1.w;
        }
        #pragma unroll
        for (int i = 0; i < 8; i++) sPart[w][c8 + i] = acc8[i];
    }
    __syncthreads();

    // Phase 4: sum the two group-half partials, coalesced 16B row store.
    {
        float4 v;
        v.x = sPart[0][tt] + sPart[1][tt];
        v.y = sPart[2][tt] + sPart[3][tt];
        v.z = sPart[4][tt] + sPart[5][tt];
        v.w = sPart[6][tt] + sPart[7][tt];
        *(float4*)(out + (size_t)tt * NP + pix0) = v;
    }
}

// ---------------------------------------------------------------------------
extern "C" void kernel_launch(void* const* d_in, const int* in_sizes, int n_in,
                              void* d_out, int out_size) {
    const float* gar  = (const float*)d_in[0];
    const float* cond = (const float*)d_in[1];
    const float* mask = (const float*)d_in[2];
    const float* W1   = (const float*)d_in[3];
    const float* b1   = (const float*)d_in[4];
    const float* W2   = (const float*)d_in[5];
    const float* b2   = (const float*)d_in[6];
    const float* W3   = (const float*)d_in[7];
    const float* b3   = (const float*)d_in[8];
    const float* W4   = (const float*)d_in[9];
    const float* b4   = (const float*)d_in[10];
    float* out = (float*)d_out;

    float* S = nullptr;
    cudaGetSymbolAddress((void**)&S, g_scratch);
    __nv_bfloat16* inTb  = (__nv_bfloat16*)(S + OFF_INT);
    __half*        garTh = (__half*)       (S + OFF_GART);
    __nv_bfloat16* wb1   = (__nv_bfloat16*)(S + OFF_WB1);
    __nv_bfloat16* wb2   = (__nv_bfloat16*)(S + OFF_WB2);
    __nv_bfloat16* wb3   = (__nv_bfloat16*)(S + OFF_WB3);
    __nv_bfloat16* wb4   = (__nv_bfloat16*)(S + OFF_WB4);
    __nv_bfloat16* h1    = (__nv_bfloat16*)(S + OFF_H1);
    __nv_bfloat16* h2    = (__nv_bfloat16*)(S + OFF_H2);
    __nv_bfloat16* h3    = (__nv_bfloat16*)(S + OFF_H3);
    float*         oa    = S + OFF_OA;

    // dynamic smem: band + B stages (+1KB align slack)
    const int SM1  = 264 * 128 + 3 * 128 * 128 + 1024;  // 83968 -> 2 CTAs/SM
    const int SM2  = 264 * 128 + 3 * 64 * 128 + 1024;   // 59392 -> 3 CTAs/SM
    const int SM34 = 264 * 128 + 9 * 32 * 128 + 1024;   // 71680 -> 3 CTAs/SM

    cudaFuncSetAttribute(mconv<512,128,128,128,true ,0,2>, cudaFuncAttributeMaxDynamicSharedMemorySize, SM1);
    cudaFuncSetAttribute(mconv<128, 64, 64, 64,true ,0,3>, cudaFuncAttributeMaxDynamicSharedMemorySize, SM2);
    cudaFuncSetAttribute(mconv< 64, 32, 32, 64,true ,0,3>, cudaFuncAttributeMaxDynamicSharedMemorySize, SM34);
    cudaFuncSetAttribute(mconv< 64, 32, 18,  1,false,1,3>, cudaFuncAttributeMaxDynamicSharedMemorySize, SM34);

    prep_all<<<2048 + 2752, 256>>>(gar, cond, inTb, garTh,
                                   W1, wb1, W2, wb2, W3, wb3, W4, wb4);

    mconv<512,128,128,128,true ,0,2><<<dim3(32, 8), 128, SM1 >>>(inTb, 0,               wb1, b1, h1);
    mconv<128, 64, 64, 64,true ,0,3><<<dim3(32, 8), 128, SM2 >>>(h1, (size_t)NP * 128,  wb2, b2, h2);
    mconv< 64, 32, 32, 64,true ,0,3><<<dim3(32, 8), 128, SM34>>>(h2, (size_t)NP * 64,   wb3, b3, h3);
    mconv< 64, 32, 18,  1,false,1,3><<<dim3(32, 8), 128, SM34>>>(h3, (size_t)NP * 64,   wb4, b4, oa);

    warp_kernel<<<NP / 4, 256>>>(oa, garTh, mask, out);
}